// round 1
// baseline (speedup 1.0000x reference)
#include <cuda_runtime.h>
#include <math.h>

// DeepFM fused inference kernel — fp32 CUDA-core baseline.
// B=262144 rows, per-row: gather -> FM linear -> FM cross (128x128 x2) ->
// MLP 128->200->256->200->128->1 -> sigmoid.
//
// Strategy: one CTA per 64-row tile. Activations live in dynamic smem
// (ping-pong buffers). Each thread owns one output column j and
// register-blocks 8 rows: per inner step 1 coalesced global W load +
// 8 broadcast LDS.128 feed 32 FFMAs, so the fp32 FMA pipe binds.

#define TM 64          // rows per CTA
#define NTHREADS 256   // threads per CTA (8 warps)
#define RB 8           // row register-blocking factor
#define HASH_BINS 100000

template<int K, int N, bool RELU>
__device__ __forceinline__ void layer_ff(const float* __restrict__ in_s,   // [TM][K] smem
                                         float* __restrict__ out_s,        // [TM][N] smem
                                         const float* __restrict__ W,      // [K][N] gmem
                                         const float* __restrict__ bias,   // [N] gmem
                                         int tid)
{
    if (tid < N) {
        const int j = tid;
        const float bj = __ldg(&bias[j]);
        for (int r0 = 0; r0 < TM; r0 += RB) {
            float acc[RB];
#pragma unroll
            for (int rr = 0; rr < RB; rr++) acc[rr] = bj;
#pragma unroll 2
            for (int k = 0; k < K; k += 4) {
                const float w0 = __ldg(&W[(k + 0) * N + j]);
                const float w1 = __ldg(&W[(k + 1) * N + j]);
                const float w2 = __ldg(&W[(k + 2) * N + j]);
                const float w3 = __ldg(&W[(k + 3) * N + j]);
#pragma unroll
                for (int rr = 0; rr < RB; rr++) {
                    const float4 x = *reinterpret_cast<const float4*>(&in_s[(r0 + rr) * K + k]);
                    acc[rr] = fmaf(x.x, w0, acc[rr]);
                    acc[rr] = fmaf(x.y, w1, acc[rr]);
                    acc[rr] = fmaf(x.z, w2, acc[rr]);
                    acc[rr] = fmaf(x.w, w3, acc[rr]);
                }
            }
#pragma unroll
            for (int rr = 0; rr < RB; rr++) {
                float v = acc[rr];
                if (RELU) v = fmaxf(v, 0.0f);
                out_s[(r0 + rr) * N + j] = v;
            }
        }
    }
    __syncthreads();
}

__global__ __launch_bounds__(NTHREADS, 1)
void dfm_kernel(
    const int* __restrict__ user_idx, const int* __restrict__ item_idx,
    const float* __restrict__ user_emb, const float* __restrict__ item_emb,
    const float* __restrict__ lin_w, const float* __restrict__ lin_b,
    const float* __restrict__ cross_k,
    const float* __restrict__ W1, const float* __restrict__ b1,
    const float* __restrict__ W2, const float* __restrict__ b2,
    const float* __restrict__ W3, const float* __restrict__ b3,
    const float* __restrict__ W4, const float* __restrict__ b4,
    const float* __restrict__ W5, const float* __restrict__ b5,
    float* __restrict__ out)
{
    extern __shared__ float smem[];
    float* xs     = smem;                 // [TM][128] concatenated embeddings
    float* bufA   = xs + TM * 128;        // [TM][<=256] activations ping
    float* bufB   = bufA + TM * 256;      // [TM][<=256] activations pong
    float* rowacc = bufB + TM * 256;      // [TM] linear + cross accumulator

    const int tid  = threadIdx.x;
    const int row0 = blockIdx.x * TM;

    // ---- gather embeddings into smem (coalesced: 128 consecutive threads
    //      cover one row's 128 floats) ----
    for (int i = tid; i < TM * 128; i += NTHREADS) {
        const int r = i >> 7;
        const int k = i & 127;
        const int g = row0 + r;
        float v;
        if (k < 64) v = __ldg(&user_emb[user_idx[g] * 64 + k]);
        else        v = __ldg(&item_emb[item_idx[g] * 64 + (k - 64)]);
        xs[i] = v;
    }
    // ---- FM linear term ----
    for (int r = tid; r < TM; r += NTHREADS) {
        const int g = row0 + r;
        rowacc[r] = __ldg(&lin_w[user_idx[g]]) + __ldg(&lin_w[HASH_BINS + item_idx[g]])
                  + __ldg(&lin_b[0]);
    }
    __syncthreads();

    // ---- FM cross term: 0.5 * mean_j( (x@K)_j^2 - (x^2 @ K^2)_j ) ----
    if (tid < 128) {
        const int j = tid;
        for (int r0 = 0; r0 < TM; r0 += RB) {
            float a[RB], bq[RB];
#pragma unroll
            for (int rr = 0; rr < RB; rr++) { a[rr] = 0.0f; bq[rr] = 0.0f; }
#pragma unroll 2
            for (int k = 0; k < 128; k += 4) {
                const float c0 = __ldg(&cross_k[(k + 0) * 128 + j]);
                const float c1 = __ldg(&cross_k[(k + 1) * 128 + j]);
                const float c2 = __ldg(&cross_k[(k + 2) * 128 + j]);
                const float c3 = __ldg(&cross_k[(k + 3) * 128 + j]);
                const float s0 = c0 * c0, s1 = c1 * c1, s2 = c2 * c2, s3 = c3 * c3;
#pragma unroll
                for (int rr = 0; rr < RB; rr++) {
                    const float4 x = *reinterpret_cast<const float4*>(&xs[(r0 + rr) * 128 + k]);
                    a[rr]  = fmaf(x.x, c0, a[rr]);
                    a[rr]  = fmaf(x.y, c1, a[rr]);
                    a[rr]  = fmaf(x.z, c2, a[rr]);
                    a[rr]  = fmaf(x.w, c3, a[rr]);
                    bq[rr] = fmaf(x.x * x.x, s0, bq[rr]);
                    bq[rr] = fmaf(x.y * x.y, s1, bq[rr]);
                    bq[rr] = fmaf(x.z * x.z, s2, bq[rr]);
                    bq[rr] = fmaf(x.w * x.w, s3, bq[rr]);
                }
            }
#pragma unroll
            for (int rr = 0; rr < RB; rr++) {
                const float contrib = 0.5f * (a[rr] * a[rr] - bq[rr]) * (1.0f / 128.0f);
                atomicAdd(&rowacc[r0 + rr], contrib);
            }
        }
    }
    __syncthreads();

    // ---- Deep MLP ----
    layer_ff<128, 200, true>(xs,   bufA, W1, b1, tid);
    layer_ff<200, 256, true>(bufA, bufB, W2, b2, tid);
    layer_ff<256, 200, true>(bufB, bufA, W3, b3, tid);
    layer_ff<200, 128, true>(bufA, bufB, W4, b4, tid);

    // ---- final Dense(1) + sigmoid (one thread per row) ----
    for (int r = tid; r < TM; r += NTHREADS) {
        float acc = __ldg(&b5[0]);
#pragma unroll
        for (int k = 0; k < 128; k += 4) {
            const float4 x = *reinterpret_cast<const float4*>(&bufB[r * 128 + k]);
            acc = fmaf(x.x, __ldg(&W5[k + 0]), acc);
            acc = fmaf(x.y, __ldg(&W5[k + 1]), acc);
            acc = fmaf(x.z, __ldg(&W5[k + 2]), acc);
            acc = fmaf(x.w, __ldg(&W5[k + 3]), acc);
        }
        const float logit = acc + rowacc[r];
        out[row0 + r] = 1.0f / (1.0f + expf(-logit));
    }
}

extern "C" void kernel_launch(void* const* d_in, const int* in_sizes, int n_in,
                              void* d_out, int out_size)
{
    const int*   user_idx = (const int*)d_in[0];
    const int*   item_idx = (const int*)d_in[1];
    const float* user_emb = (const float*)d_in[2];
    const float* item_emb = (const float*)d_in[3];
    const float* lin_w    = (const float*)d_in[4];
    const float* lin_b    = (const float*)d_in[5];
    const float* cross_k  = (const float*)d_in[6];
    const float* W1 = (const float*)d_in[7];  const float* b1 = (const float*)d_in[8];
    const float* W2 = (const float*)d_in[9];  const float* b2 = (const float*)d_in[10];
    const float* W3 = (const float*)d_in[11]; const float* b3 = (const float*)d_in[12];
    const float* W4 = (const float*)d_in[13]; const float* b4 = (const float*)d_in[14];
    const float* W5 = (const float*)d_in[15]; const float* b5 = (const float*)d_in[16];
    float* out = (float*)d_out;

    const int B = in_sizes[0];
    const int smem_bytes = (TM * 128 + 2 * TM * 256 + TM) * (int)sizeof(float);  // 164 KB

    cudaFuncSetAttribute(dfm_kernel, cudaFuncAttributeMaxDynamicSharedMemorySize, smem_bytes);

    const int nblocks = B / TM;  // B = 262144, TM = 64 -> 4096 CTAs
    dfm_kernel<<<nblocks, NTHREADS, smem_bytes>>>(
        user_idx, item_idx, user_emb, item_emb, lin_w, lin_b, cross_k,
        W1, b1, W2, b2, W3, b3, W4, b4, W5, b5, out);
}

// round 2
// speedup vs baseline: 11.7912x; 11.7912x over previous
#include <cuda_runtime.h>
#include <math.h>
#include <stdint.h>

// DeepFM fused inference — tf32 tensor-core (mma.sync.m16n8k8) version.
// Per CTA: 64 rows. 8 warps = 4 row-warps x 2 n-half groups.
// Weights pre-packed into per-lane MMA B-fragment order by a prep kernel.

#define HASH_BINS 100000
#define M_TILE 64
#define NTHREADS 256

// Activation smem strides (floats). stride % 8 == 4 makes the A-fragment
// LDS pattern conflict-free: bank = (stride*gid + tig) % 32 == perm(lane).
#define S128 132
#define S200 204
#define S256 260

// ---------------- packed weight scratch (device globals, no allocs) --------
__device__ float g_Kp [16 * 16 * 64];   // cross_k           KT=16 NTOT=16
__device__ float g_K2p[16 * 16 * 64];   // cross_k^2
__device__ float g_W1p[16 * 25 * 64];   // W1 128->200       KT=16 NTOT=25
__device__ float g_W2p[25 * 32 * 64];   // W2 200->256       KT=25 NTOT=32
__device__ float g_W3p[32 * 25 * 64];   // W3 256->200       KT=32 NTOT=25
__device__ float g_W4p[25 * 16 * 64];   // W4 200->128       KT=25 NTOT=16

__device__ __forceinline__ float tf32_round(float x) {
    uint32_t u;
    asm("cvt.rna.tf32.f32 %0, %1;" : "=r"(u) : "f"(x));
    return __uint_as_float(u);
}

__device__ __forceinline__ void mma_tf32(float d[4],
                                         uint32_t a0, uint32_t a1, uint32_t a2, uint32_t a3,
                                         uint32_t b0, uint32_t b1) {
    asm volatile(
        "mma.sync.aligned.m16n8k8.row.col.f32.tf32.tf32.f32 "
        "{%0,%1,%2,%3}, {%4,%5,%6,%7}, {%8,%9}, {%0,%1,%2,%3};\n"
        : "+f"(d[0]), "+f"(d[1]), "+f"(d[2]), "+f"(d[3])
        : "r"(a0), "r"(a1), "r"(a2), "r"(a3), "r"(b0), "r"(b1));
}

// ---------------- prep: pack W[K][N] into B-fragment order -----------------
// packed[((kt*NTOT + nt)*32 + lane)*2 + s] = tf32( W[(kt*8 + lane%4 + 4s)*N + nt*8 + lane/4] )
__device__ __forceinline__ void pack_seg(float* dst, const float* __restrict__ src,
                                         int NTOT, int N, int idx, bool square) {
    const int kt   = idx / (NTOT * 64);
    const int r    = idx % (NTOT * 64);
    const int nt   = r >> 6;
    const int l2   = r & 63;
    const int lane = l2 >> 1;
    const int s    = l2 & 1;
    const int k    = kt * 8 + (lane & 3) + s * 4;
    const int n    = nt * 8 + (lane >> 2);
    float v = src[k * N + n];
    if (square) v *= v;
    dst[idx] = tf32_round(v);
}

__global__ void pack_kernel(const float* __restrict__ cross_k,
                            const float* __restrict__ W1, const float* __restrict__ W2,
                            const float* __restrict__ W3, const float* __restrict__ W4) {
    const int i = blockIdx.x * blockDim.x + threadIdx.x;
    const int s0 = 16 * 16 * 64;             // Kp
    const int s1 = s0 + 16 * 16 * 64;        // K2p
    const int s2 = s1 + 16 * 25 * 64;        // W1p
    const int s3 = s2 + 25 * 32 * 64;        // W2p
    const int s4 = s3 + 32 * 25 * 64;        // W3p
    const int s5 = s4 + 25 * 16 * 64;        // W4p
    if (i < s0)       pack_seg(g_Kp,  cross_k, 16, 128, i,       false);
    else if (i < s1)  pack_seg(g_K2p, cross_k, 16, 128, i - s0,  true);
    else if (i < s2)  pack_seg(g_W1p, W1,      25, 200, i - s1,  false);
    else if (i < s3)  pack_seg(g_W2p, W2,      32, 256, i - s2,  false);
    else if (i < s4)  pack_seg(g_W3p, W3,      25, 200, i - s3,  false);
    else if (i < s5)  pack_seg(g_W4p, W4,      16, 128, i - s4,  false);
}

// ---------------- one GEMM chunk: 16 rows x (NT*8) cols over full K --------
template<int NT, bool RELU, bool ROUND>
__device__ __forceinline__ void gemm_chunk(
    const float* __restrict__ Xs, int xs,        // activations [64][xs] smem
    float* __restrict__ Ys, int ys,              // output      [64][ys] smem
    const float* __restrict__ Wp,                // packed weights
    const float* __restrict__ bias,
    int KT, int NTOT, int row0, int nt0, int lane)
{
    float acc[NT][4];
#pragma unroll
    for (int t = 0; t < NT; t++) { acc[t][0] = acc[t][1] = acc[t][2] = acc[t][3] = 0.0f; }
    const int gid = lane >> 2, tig = lane & 3;
    const float* xr0 = Xs + (row0 + gid)     * xs;
    const float* xr1 = Xs + (row0 + gid + 8) * xs;

    for (int kt = 0; kt < KT; kt++) {
        const int c = kt * 8 + tig;
        const uint32_t a0 = __float_as_uint(xr0[c]);
        const uint32_t a1 = __float_as_uint(xr1[c]);
        const uint32_t a2 = __float_as_uint(xr0[c + 4]);
        const uint32_t a3 = __float_as_uint(xr1[c + 4]);
        const float* wp = Wp + ((size_t)(kt * NTOT + nt0) * 64) + lane * 2;
#pragma unroll
        for (int t = 0; t < NT; t++) {
            const float2 b = *reinterpret_cast<const float2*>(wp + t * 64);
            mma_tf32(acc[t], a0, a1, a2, a3, __float_as_uint(b.x), __float_as_uint(b.y));
        }
    }
#pragma unroll
    for (int t = 0; t < NT; t++) {
        const int col = (nt0 + t) * 8 + 2 * tig;
        const float bc0 = __ldg(&bias[col]);
        const float bc1 = __ldg(&bias[col + 1]);
        float v0 = acc[t][0] + bc0, v1 = acc[t][1] + bc1;
        float v2 = acc[t][2] + bc0, v3 = acc[t][3] + bc1;
        if (RELU) {
            v0 = fmaxf(v0, 0.0f); v1 = fmaxf(v1, 0.0f);
            v2 = fmaxf(v2, 0.0f); v3 = fmaxf(v3, 0.0f);
        }
        if (ROUND) { v0 = tf32_round(v0); v1 = tf32_round(v1); v2 = tf32_round(v2); v3 = tf32_round(v3); }
        Ys[(row0 + gid)     * ys + col]     = v0;
        Ys[(row0 + gid)     * ys + col + 1] = v1;
        Ys[(row0 + gid + 8) * ys + col]     = v2;
        Ys[(row0 + gid + 8) * ys + col + 1] = v3;
    }
}

// ---------------- FM cross chunk: P = xK, Q = x^2 K^2, reduce to rowacc ----
template<int NT>
__device__ __forceinline__ void cross_chunk(
    const float* __restrict__ Xs, int xs,
    int row0, int nt0, int NTOT, int lane, float* __restrict__ rowacc)
{
    float p[NT][4], q[NT][4];
#pragma unroll
    for (int t = 0; t < NT; t++) {
        p[t][0] = p[t][1] = p[t][2] = p[t][3] = 0.0f;
        q[t][0] = q[t][1] = q[t][2] = q[t][3] = 0.0f;
    }
    const int gid = lane >> 2, tig = lane & 3;
    const float* xr0 = Xs + (row0 + gid)     * xs;
    const float* xr1 = Xs + (row0 + gid + 8) * xs;

    for (int kt = 0; kt < 16; kt++) {
        const int c = kt * 8 + tig;
        const float x0 = xr0[c], x1 = xr1[c], x2 = xr0[c + 4], x3 = xr1[c + 4];
        const uint32_t a0 = __float_as_uint(x0), a1 = __float_as_uint(x1);
        const uint32_t a2 = __float_as_uint(x2), a3 = __float_as_uint(x3);
        const uint32_t u0 = __float_as_uint(tf32_round(x0 * x0));
        const uint32_t u1 = __float_as_uint(tf32_round(x1 * x1));
        const uint32_t u2 = __float_as_uint(tf32_round(x2 * x2));
        const uint32_t u3 = __float_as_uint(tf32_round(x3 * x3));
        const size_t off = (size_t)(kt * NTOT + nt0) * 64 + lane * 2;
        const float* wp1 = g_Kp  + off;
        const float* wp2 = g_K2p + off;
#pragma unroll
        for (int t = 0; t < NT; t++) {
            const float2 b1v = *reinterpret_cast<const float2*>(wp1 + t * 64);
            mma_tf32(p[t], a0, a1, a2, a3, __float_as_uint(b1v.x), __float_as_uint(b1v.y));
            const float2 b2v = *reinterpret_cast<const float2*>(wp2 + t * 64);
            mma_tf32(q[t], u0, u1, u2, u3, __float_as_uint(b2v.x), __float_as_uint(b2v.y));
        }
    }
    float s_r = 0.0f, s_r8 = 0.0f;
#pragma unroll
    for (int t = 0; t < NT; t++) {
        s_r  += p[t][0] * p[t][0] - q[t][0] + p[t][1] * p[t][1] - q[t][1];
        s_r8 += p[t][2] * p[t][2] - q[t][2] + p[t][3] * p[t][3] - q[t][3];
    }
    s_r  += __shfl_xor_sync(0xffffffffu, s_r, 1);
    s_r  += __shfl_xor_sync(0xffffffffu, s_r, 2);
    s_r8 += __shfl_xor_sync(0xffffffffu, s_r8, 1);
    s_r8 += __shfl_xor_sync(0xffffffffu, s_r8, 2);
    if (tig == 0) {
        const float sc = 0.5f / 128.0f;
        atomicAdd(&rowacc[row0 + gid],     sc * s_r);
        atomicAdd(&rowacc[row0 + gid + 8], sc * s_r8);
    }
}

// ---------------- main kernel ---------------------------------------------
__global__ __launch_bounds__(NTHREADS, 1)
void dfm_tc_kernel(
    const int* __restrict__ user_idx, const int* __restrict__ item_idx,
    const float* __restrict__ user_emb, const float* __restrict__ item_emb,
    const float* __restrict__ lin_w, const float* __restrict__ lin_b,
    const float* __restrict__ b1, const float* __restrict__ b2,
    const float* __restrict__ b3, const float* __restrict__ b4,
    const float* __restrict__ W5, const float* __restrict__ b5,
    float* __restrict__ out)
{
    extern __shared__ float smem[];
    // Arena layout (floats):
    //   ping  [64][S200]                        : 13056
    //   arenaB = union{ X0 [64][S128], pong [64][S256], X4 [64][S128] } : 16640
    //   rowacc[64]
    float* ping   = smem;
    float* arenaB = ping + M_TILE * S200;
    float* rowacc = arenaB + M_TILE * S256;
    float* X0   = arenaB;   // stride S128, live: gather..layer1
    float* pong = arenaB;   // stride S256, live: layer2..layer3
    float* X4   = arenaB;   // stride S128, live: layer4..layer5

    const int tid  = threadIdx.x;
    const int lane = tid & 31;
    const int w    = tid >> 5;
    const int roww = w & 3;          // which 16-row slab
    const int nhalf = w >> 2;        // n-dimension half
    const int row0 = roww * 16;
    const int grow0 = blockIdx.x * M_TILE;

    // ---- gather embeddings (tf32-rounded) + FM linear term ----
    for (int i = tid; i < M_TILE * 128; i += NTHREADS) {
        const int r = i >> 7;
        const int c = i & 127;
        const int g = grow0 + r;
        float v;
        if (c < 64) v = __ldg(&user_emb[user_idx[g] * 64 + c]);
        else        v = __ldg(&item_emb[item_idx[g] * 64 + (c - 64)]);
        X0[r * S128 + c] = tf32_round(v);
    }
    for (int r = tid; r < M_TILE; r += NTHREADS) {
        const int g = grow0 + r;
        rowacc[r] = __ldg(&lin_w[user_idx[g]]) + __ldg(&lin_w[HASH_BINS + item_idx[g]])
                  + __ldg(&lin_b[0]);
    }
    __syncthreads();

    // ---- FM cross term (N=128, halves of 8 tiles) ----
    cross_chunk<8>(X0, S128, row0, nhalf * 8, 16, lane, rowacc);

    // ---- layer 1: 128 -> 200 (relu), X0 -> ping ----
    if (nhalf == 0) {
        gemm_chunk<8, true, true>(X0, S128, ping, S200, g_W1p, b1, 16, 25, row0, 0,  lane);
        gemm_chunk<5, true, true>(X0, S128, ping, S200, g_W1p, b1, 16, 25, row0, 8,  lane);
    } else {
        gemm_chunk<8, true, true>(X0, S128, ping, S200, g_W1p, b1, 16, 25, row0, 13, lane);
        gemm_chunk<4, true, true>(X0, S128, ping, S200, g_W1p, b1, 16, 25, row0, 21, lane);
    }
    __syncthreads();

    // ---- layer 2: 200 -> 256 (relu), ping -> pong (X0 dead) ----
    {
        const int base = nhalf * 16;
        gemm_chunk<8, true, true>(ping, S200, pong, S256, g_W2p, b2, 25, 32, row0, base,     lane);
        gemm_chunk<8, true, true>(ping, S200, pong, S256, g_W2p, b2, 25, 32, row0, base + 8, lane);
    }
    __syncthreads();

    // ---- layer 3: 256 -> 200 (relu), pong -> ping ----
    if (nhalf == 0) {
        gemm_chunk<8, true, true>(pong, S256, ping, S200, g_W3p, b3, 32, 25, row0, 0,  lane);
        gemm_chunk<5, true, true>(pong, S256, ping, S200, g_W3p, b3, 32, 25, row0, 8,  lane);
    } else {
        gemm_chunk<8, true, true>(pong, S256, ping, S200, g_W3p, b3, 32, 25, row0, 13, lane);
        gemm_chunk<4, true, true>(pong, S256, ping, S200, g_W3p, b3, 32, 25, row0, 21, lane);
    }
    __syncthreads();

    // ---- layer 4: 200 -> 128 (relu), ping -> X4 (pong dead); keep fp32 ----
    gemm_chunk<8, true, false>(ping, S200, X4, S128, g_W4p, b4, 25, 16, row0, nhalf * 8, lane);
    __syncthreads();

    // ---- layer 5: Dense(1) + linear + cross + sigmoid ----
    if (tid < M_TILE) {
        const int r = tid;
        float acc = __ldg(&b5[0]);
#pragma unroll 8
        for (int k = 0; k < 128; k++) {
            acc = fmaf(X4[r * S128 + k], __ldg(&W5[k]), acc);
        }
        const float logit = acc + rowacc[r];
        out[grow0 + r] = 1.0f / (1.0f + expf(-logit));
    }
}

extern "C" void kernel_launch(void* const* d_in, const int* in_sizes, int n_in,
                              void* d_out, int out_size)
{
    const int*   user_idx = (const int*)d_in[0];
    const int*   item_idx = (const int*)d_in[1];
    const float* user_emb = (const float*)d_in[2];
    const float* item_emb = (const float*)d_in[3];
    const float* lin_w    = (const float*)d_in[4];
    const float* lin_b    = (const float*)d_in[5];
    const float* cross_k  = (const float*)d_in[6];
    const float* W1 = (const float*)d_in[7];  const float* b1 = (const float*)d_in[8];
    const float* W2 = (const float*)d_in[9];  const float* b2 = (const float*)d_in[10];
    const float* W3 = (const float*)d_in[11]; const float* b3 = (const float*)d_in[12];
    const float* W4 = (const float*)d_in[13]; const float* b4 = (const float*)d_in[14];
    const float* W5 = (const float*)d_in[15]; const float* b5 = (const float*)d_in[16];
    float* out = (float*)d_out;

    const int B = in_sizes[0];

    // prep: pack weights into MMA fragment order
    const int total_pack = (16*16 + 16*16 + 16*25 + 25*32 + 32*25 + 25*16) * 64;
    pack_kernel<<<(total_pack + 255) / 256, 256>>>(cross_k, W1, W2, W3, W4);

    const int smem_bytes = (M_TILE * S200 + M_TILE * S256 + M_TILE) * (int)sizeof(float);
    static bool attr_set = false;
    if (!attr_set) {
        cudaFuncSetAttribute(dfm_tc_kernel, cudaFuncAttributeMaxDynamicSharedMemorySize, smem_bytes);
        attr_set = true;
    }

    dfm_tc_kernel<<<B / M_TILE, NTHREADS, smem_bytes>>>(
        user_idx, item_idx, user_emb, item_emb, lin_w, lin_b,
        b1, b2, b3, b4, W5, b5, out);
}

// round 4
// speedup vs baseline: 26.5127x; 2.2485x over previous
#include <cuda_runtime.h>
#include <cuda_bf16.h>
#include <math.h>
#include <stdint.h>

// DeepFM fused inference — bf16 mma.sync.m16n8k16 + 2 CTAs/SM.
// Per CTA: 64 rows, 8 warps = 4 row-slabs x 2 n-halves.
// Weights pre-packed (pair-of-tiles -> one LDG.128) by a prep kernel.
// All layer widths zero-padded to multiples of 16 (200 -> 208).

#define HASH_BINS 100000
#define M_TILE 64
#define NTHREADS 256

// Activation smem strides in 32-bit WORDS (2 bf16 per word).
// stride % 8 == 4 -> conflict-free A-fragment LDS and epilogue STS.
#define W128 68
#define W208 108
#define W256 132
#define F128 132   // fp32 stride for final activation buffer

// ---------------- packed weight scratch (device globals) -------------------
// Layout: word[(((kt*NP + np)*32 + lane)*4 + t*2 + s)]
//   tile nt = np*2 + t, n = nt*8 + lane/4, k = kt*16 + s*8 + 2*(lane%4) (+1)
__device__ uint32_t g_Kp [ 8 *  8 * 128];   // cross_k    K=128 N=128
__device__ uint32_t g_K2p[ 8 *  8 * 128];   // cross_k^2
__device__ uint32_t g_W1p[ 8 * 13 * 128];   // W1 128->208
__device__ uint32_t g_W2p[13 * 16 * 128];   // W2 208->256
__device__ uint32_t g_W3p[16 * 13 * 128];   // W3 256->208
__device__ uint32_t g_W4p[13 *  8 * 128];   // W4 208->128
__device__ float    g_b1p[208];
__device__ float    g_b2p[256];
__device__ float    g_b3p[208];
__device__ float    g_b4p[128];

__device__ __forceinline__ uint32_t pack_bf2(float lo, float hi) {
    __nv_bfloat162 h = __floats2bfloat162_rn(lo, hi);
    return *reinterpret_cast<uint32_t*>(&h);
}

__device__ __forceinline__ void mma_bf16(float d[4],
                                         uint32_t a0, uint32_t a1, uint32_t a2, uint32_t a3,
                                         uint32_t b0, uint32_t b1) {
    asm volatile(
        "mma.sync.aligned.m16n8k16.row.col.f32.bf16.bf16.f32 "
        "{%0,%1,%2,%3}, {%4,%5,%6,%7}, {%8,%9}, {%0,%1,%2,%3};\n"
        : "+f"(d[0]), "+f"(d[1]), "+f"(d[2]), "+f"(d[3])
        : "r"(a0), "r"(a1), "r"(a2), "r"(a3), "r"(b0), "r"(b1));
}

// ---------------- prep kernel ---------------------------------------------
__device__ __forceinline__ void pack_w(uint32_t* dst, const float* __restrict__ src,
                                       int K_real, int N_real, int NP, int idx, bool square) {
    const int j    = idx & 3;
    const int lane = (idx >> 2) & 31;
    const int tp   = idx >> 7;
    const int np   = tp % NP;
    const int kt   = tp / NP;
    const int t = j >> 1, s = j & 1;
    const int n  = (np * 2 + t) * 8 + (lane >> 2);
    const int k0 = kt * 16 + s * 8 + 2 * (lane & 3);
    float v0 = (k0     < K_real && n < N_real) ? src[(size_t)k0 * N_real + n]       : 0.0f;
    float v1 = (k0 + 1 < K_real && n < N_real) ? src[(size_t)(k0 + 1) * N_real + n] : 0.0f;
    if (square) { v0 *= v0; v1 *= v1; }
    dst[idx] = pack_bf2(v0, v1);
}

#define SZ_KP  (8 * 8 * 128)
#define SZ_W1  (8 * 13 * 128)
#define SZ_W2  (13 * 16 * 128)
#define SZ_W3  (16 * 13 * 128)
#define SZ_W4  (13 * 8 * 128)

__global__ void pack_kernel(const float* __restrict__ cross_k,
                            const float* __restrict__ W1, const float* __restrict__ W2,
                            const float* __restrict__ W3, const float* __restrict__ W4,
                            const float* __restrict__ b1, const float* __restrict__ b2,
                            const float* __restrict__ b3, const float* __restrict__ b4) {
    const int i = blockIdx.x * blockDim.x + threadIdx.x;
    const int E0 = SZ_KP, E1 = E0 + SZ_KP, E2 = E1 + SZ_W1, E3 = E2 + SZ_W2;
    const int E4 = E3 + SZ_W3, E5 = E4 + SZ_W4;
    if      (i < E0) pack_w(g_Kp,  cross_k, 128, 128,  8, i,      false);
    else if (i < E1) pack_w(g_K2p, cross_k, 128, 128,  8, i - E0, true);
    else if (i < E2) pack_w(g_W1p, W1,      128, 200, 13, i - E1, false);
    else if (i < E3) pack_w(g_W2p, W2,      200, 256, 16, i - E2, false);
    else if (i < E4) pack_w(g_W3p, W3,      256, 200, 13, i - E3, false);
    else if (i < E5) pack_w(g_W4p, W4,      200, 128,  8, i - E4, false);
    else {
        int j = i - E5;
        if      (j < 208) g_b1p[j]       = (j < 200) ? b1[j] : 0.0f;
        else if (j < 464) g_b2p[j - 208] = b2[j - 208];
        else if (j < 672) g_b3p[j - 464] = (j - 464 < 200) ? b3[j - 464] : 0.0f;
        else if (j < 800) g_b4p[j - 672] = b4[j - 672];
    }
}
#define PACK_TOTAL (SZ_KP + SZ_KP + SZ_W1 + SZ_W2 + SZ_W3 + SZ_W4 + 800)

// ---------------- GEMM chunk: 16 rows x 2 pairs (4 tiles) -----------------
template<int NPAIR, bool F32OUT>
__device__ __forceinline__ void gemm_chunk(
    const uint32_t* __restrict__ Xw, int xstride,
    void* __restrict__ Yout, int ystride,
    const uint32_t* __restrict__ Wp, const float* __restrict__ biasp,
    int KT, int NP, int row0, int np0, int lane)
{
    const int NT = NPAIR * 2;
    float acc[NPAIR * 2][4];
#pragma unroll
    for (int t = 0; t < NT; t++) { acc[t][0] = acc[t][1] = acc[t][2] = acc[t][3] = 0.0f; }
    const int gid = lane >> 2, tig = lane & 3;
    const uint32_t* xr0 = Xw + (row0 + gid)     * xstride;
    const uint32_t* xr1 = Xw + (row0 + gid + 8) * xstride;

    for (int kt = 0; kt < KT; kt++) {
        const int w = kt * 8 + tig;
        const uint32_t a0 = xr0[w], a1 = xr1[w], a2 = xr0[w + 4], a3 = xr1[w + 4];
        const uint4* bp = reinterpret_cast<const uint4*>(Wp + (((size_t)kt * NP + np0) * 32 + lane) * 4);
#pragma unroll
        for (int p = 0; p < NPAIR; p++) {
            const uint4 B = bp[p * 32];
            mma_bf16(acc[p * 2],     a0, a1, a2, a3, B.x, B.y);
            mma_bf16(acc[p * 2 + 1], a0, a1, a2, a3, B.z, B.w);
        }
    }
#pragma unroll
    for (int t = 0; t < NT; t++) {
        const int nt  = np0 * 2 + t;
        const int col = nt * 8 + 2 * tig;
        const float bc0 = biasp[col], bc1 = biasp[col + 1];
        float v0 = fmaxf(acc[t][0] + bc0, 0.0f);
        float v1 = fmaxf(acc[t][1] + bc1, 0.0f);
        float v2 = fmaxf(acc[t][2] + bc0, 0.0f);
        float v3 = fmaxf(acc[t][3] + bc1, 0.0f);
        if (F32OUT) {
            float* Y = reinterpret_cast<float*>(Yout);
            Y[(row0 + gid)     * ystride + col]     = v0;
            Y[(row0 + gid)     * ystride + col + 1] = v1;
            Y[(row0 + gid + 8) * ystride + col]     = v2;
            Y[(row0 + gid + 8) * ystride + col + 1] = v3;
        } else {
            uint32_t* Y = reinterpret_cast<uint32_t*>(Yout);
            Y[(row0 + gid)     * ystride + nt * 4 + tig] = pack_bf2(v0, v1);
            Y[(row0 + gid + 8) * ystride + nt * 4 + tig] = pack_bf2(v2, v3);
        }
    }
}

template<bool F32OUT>
__device__ __forceinline__ void gemm_range(
    const uint32_t* __restrict__ Xw, int xstride, void* __restrict__ Yout, int ystride,
    const uint32_t* __restrict__ Wp, const float* __restrict__ biasp,
    int KT, int NP, int row0, int np_begin, int np_end, int lane)
{
    int np = np_begin;
    for (; np + 2 <= np_end; np += 2)
        gemm_chunk<2, F32OUT>(Xw, xstride, Yout, ystride, Wp, biasp, KT, NP, row0, np, lane);
    if (np < np_end)
        gemm_chunk<1, F32OUT>(Xw, xstride, Yout, ystride, Wp, biasp, KT, NP, row0, np, lane);
}

// ---------------- FM cross chunk: 2 pairs (4 tiles) -----------------------
__device__ __forceinline__ void cross_chunk(
    const uint32_t* __restrict__ X0, const uint32_t* __restrict__ X0sq,
    int row0, int np0, int lane, float& s_r, float& s_r8)
{
    float p[4][4], q[4][4];
#pragma unroll
    for (int t = 0; t < 4; t++) {
        p[t][0] = p[t][1] = p[t][2] = p[t][3] = 0.0f;
        q[t][0] = q[t][1] = q[t][2] = q[t][3] = 0.0f;
    }
    const int gid = lane >> 2, tig = lane & 3;
    const uint32_t* xr0 = X0   + (row0 + gid)     * W128;
    const uint32_t* xr1 = X0   + (row0 + gid + 8) * W128;
    const uint32_t* ur0 = X0sq + (row0 + gid)     * W128;
    const uint32_t* ur1 = X0sq + (row0 + gid + 8) * W128;

    for (int kt = 0; kt < 8; kt++) {
        const int w = kt * 8 + tig;
        const uint32_t a0 = xr0[w], a1 = xr1[w], a2 = xr0[w + 4], a3 = xr1[w + 4];
        const uint32_t u0 = ur0[w], u1 = ur1[w], u2 = ur0[w + 4], u3 = ur1[w + 4];
        const size_t off = (((size_t)kt * 8 + np0) * 32 + lane) * 4;
        const uint4* bp1 = reinterpret_cast<const uint4*>(g_Kp  + off);
        const uint4* bp2 = reinterpret_cast<const uint4*>(g_K2p + off);
#pragma unroll
        for (int pp = 0; pp < 2; pp++) {
            const uint4 B1 = bp1[pp * 32];
            mma_bf16(p[pp * 2],     a0, a1, a2, a3, B1.x, B1.y);
            mma_bf16(p[pp * 2 + 1], a0, a1, a2, a3, B1.z, B1.w);
            const uint4 B2 = bp2[pp * 32];
            mma_bf16(q[pp * 2],     u0, u1, u2, u3, B2.x, B2.y);
            mma_bf16(q[pp * 2 + 1], u0, u1, u2, u3, B2.z, B2.w);
        }
    }
#pragma unroll
    for (int t = 0; t < 4; t++) {
        s_r  += p[t][0] * p[t][0] - q[t][0] + p[t][1] * p[t][1] - q[t][1];
        s_r8 += p[t][2] * p[t][2] - q[t][2] + p[t][3] * p[t][3] - q[t][3];
    }
}

// ---------------- main kernel ---------------------------------------------
__global__ __launch_bounds__(NTHREADS, 2)
void dfm_bf16_kernel(
    const int* __restrict__ user_idx, const int* __restrict__ item_idx,
    const float* __restrict__ user_emb, const float* __restrict__ item_emb,
    const float* __restrict__ lin_w, const float* __restrict__ lin_b,
    const float* __restrict__ W5, const float* __restrict__ b5,
    float* __restrict__ out)
{
    extern __shared__ uint32_t smem[];
    // arenaA: 8704 words  = X0[64][W128] + X0sq[64][W128]; later L3-out (stride W208)
    // arenaB: 6912 words  = ping [64][W208]  (L1 out)
    // arenaC: 8448 words  = pong [64][W256]  (L2 out); later X4 fp32 [64][F128]
    uint32_t* arenaA = smem;
    uint32_t* arenaB = arenaA + 2 * M_TILE * W128;
    uint32_t* arenaC = arenaB + M_TILE * W208;
    float*    rowacc = reinterpret_cast<float*>(arenaC + M_TILE * W256);

    uint32_t* X0    = arenaA;
    uint32_t* X0sq  = arenaA + M_TILE * W128;
    uint32_t* ping  = arenaB;
    uint32_t* pong  = arenaC;
    uint32_t* ping2 = arenaA;                          // L3 out, stride W208
    float*    X4    = reinterpret_cast<float*>(arenaC); // L4 out fp32, stride F128

    const int tid   = threadIdx.x;
    const int lane  = tid & 31;
    const int w     = tid >> 5;
    const int row0  = (w & 3) * 16;
    const int nhalf = w >> 2;
    const int grow0 = blockIdx.x * M_TILE;

    // ---- gather embeddings -> bf16 words + squares; FM linear ----
    for (int i = tid; i < M_TILE * 64; i += NTHREADS) {
        const int r = i >> 6;
        const int wd = i & 63;
        const int g = grow0 + r;
        float2 v;
        if (wd < 32) v = *reinterpret_cast<const float2*>(&user_emb[(size_t)user_idx[g] * 64 + 2 * wd]);
        else         v = *reinterpret_cast<const float2*>(&item_emb[(size_t)item_idx[g] * 64 + 2 * (wd - 32)]);
        // round to bf16 first, then square the rounded value (consistency)
        const float x0 = __bfloat162float(__float2bfloat16_rn(v.x));
        const float x1 = __bfloat162float(__float2bfloat16_rn(v.y));
        X0  [r * W128 + wd] = pack_bf2(x0, x1);
        X0sq[r * W128 + wd] = pack_bf2(x0 * x0, x1 * x1);
    }
    for (int r = tid; r < M_TILE; r += NTHREADS) {
        const int g = grow0 + r;
        rowacc[r] = __ldg(&lin_w[user_idx[g]]) + __ldg(&lin_w[HASH_BINS + item_idx[g]])
                  + __ldg(&lin_b[0]);
    }
    __syncthreads();

    // ---- FM cross: N=128 -> 8 pairs, 4 per n-half ----
    {
        float s_r = 0.0f, s_r8 = 0.0f;
        cross_chunk(X0, X0sq, row0, nhalf * 4,     lane, s_r, s_r8);
        cross_chunk(X0, X0sq, row0, nhalf * 4 + 2, lane, s_r, s_r8);
        s_r  += __shfl_xor_sync(0xffffffffu, s_r, 1);
        s_r  += __shfl_xor_sync(0xffffffffu, s_r, 2);
        s_r8 += __shfl_xor_sync(0xffffffffu, s_r8, 1);
        s_r8 += __shfl_xor_sync(0xffffffffu, s_r8, 2);
        if ((lane & 3) == 0) {
            const float sc = 0.5f / 128.0f;
            atomicAdd(&rowacc[row0 + (lane >> 2)],     sc * s_r);
            atomicAdd(&rowacc[row0 + (lane >> 2) + 8], sc * s_r8);
        }
    }

    // ---- L1: 128 -> 208, X0 -> ping ----
    if (nhalf == 0) gemm_range<false>(X0, W128, ping, W208, g_W1p, g_b1p, 8, 13, row0, 0, 7,  lane);
    else            gemm_range<false>(X0, W128, ping, W208, g_W1p, g_b1p, 8, 13, row0, 7, 13, lane);
    __syncthreads();

    // ---- L2: 208 -> 256, ping -> pong ----
    gemm_range<false>(ping, W208, pong, W256, g_W2p, g_b2p, 13, 16, row0, nhalf * 8, nhalf * 8 + 8, lane);
    __syncthreads();

    // ---- L3: 256 -> 208, pong -> ping2 (arenaA reused) ----
    if (nhalf == 0) gemm_range<false>(pong, W256, ping2, W208, g_W3p, g_b3p, 16, 13, row0, 0, 7,  lane);
    else            gemm_range<false>(pong, W256, ping2, W208, g_W3p, g_b3p, 16, 13, row0, 7, 13, lane);
    __syncthreads();

    // ---- L4: 208 -> 128, ping2 -> X4 (fp32, arenaC reused) ----
    gemm_range<true>(ping2, W208, X4, F128, g_W4p, g_b4p, 13, 8, row0, nhalf * 4, nhalf * 4 + 4, lane);
    __syncthreads();

    // ---- L5: Dense(1) + linear + cross + sigmoid ----
    if (tid < M_TILE) {
        const int r = tid;
        float acc = __ldg(&b5[0]);
#pragma unroll 8
        for (int k = 0; k < 128; k++)
            acc = fmaf(X4[r * F128 + k], __ldg(&W5[k]), acc);
        const float logit = acc + rowacc[r];
        out[grow0 + r] = 1.0f / (1.0f + expf(-logit));
    }
}

extern "C" void kernel_launch(void* const* d_in, const int* in_sizes, int n_in,
                              void* d_out, int out_size)
{
    const int*   user_idx = (const int*)d_in[0];
    const int*   item_idx = (const int*)d_in[1];
    const float* user_emb = (const float*)d_in[2];
    const float* item_emb = (const float*)d_in[3];
    const float* lin_w    = (const float*)d_in[4];
    const float* lin_b    = (const float*)d_in[5];
    const float* cross_k  = (const float*)d_in[6];
    const float* W1 = (const float*)d_in[7];  const float* b1 = (const float*)d_in[8];
    const float* W2 = (const float*)d_in[9];  const float* b2 = (const float*)d_in[10];
    const float* W3 = (const float*)d_in[11]; const float* b3 = (const float*)d_in[12];
    const float* W4 = (const float*)d_in[13]; const float* b4 = (const float*)d_in[14];
    const float* W5 = (const float*)d_in[15]; const float* b5 = (const float*)d_in[16];
    float* out = (float*)d_out;

    const int B = in_sizes[0];

    pack_kernel<<<(PACK_TOTAL + 255) / 256, 256>>>(cross_k, W1, W2, W3, W4, b1, b2, b3, b4);

    const int smem_words = 2 * M_TILE * W128 + M_TILE * W208 + M_TILE * W256 + M_TILE;
    const int smem_bytes = smem_words * 4;   // ~94.5 KB

    cudaFuncSetAttribute(dfm_bf16_kernel, cudaFuncAttributeMaxDynamicSharedMemorySize, smem_bytes);

    dfm_bf16_kernel<<<B / M_TILE, NTHREADS, smem_bytes>>>(
        user_idx, item_idx, user_emb, item_emb, lin_w, lin_b, W5, b5, out);
}

// round 6
// speedup vs baseline: 31.7690x; 1.1983x over previous
#include <cuda_runtime.h>
#include <cuda_bf16.h>
#include <math.h>
#include <stdint.h>

// DeepFM fused inference — bf16 m16n8k16, M=32 per warp (B-reuse doubled).
// Per CTA: 64 rows, 8 warps = 2 row-groups(32) x 4 n-quarters.
// Weights pre-packed (pair-of-tiles -> one LDG.128) by a prep kernel.

#define HASH_BINS 100000
#define M_TILE 64
#define NTHREADS 256

// Activation smem strides in 32-bit WORDS (2 bf16 per word).
// stride % 8 == 4 -> conflict-free A-fragment LDS and epilogue STS.
#define W128 68
#define W208 108
#define W256 132
#define F128 132   // fp32 stride for final activation buffer

// ---------------- packed weight scratch (device globals) -------------------
// word[(((kt*NP + np)*32 + lane)*4 + t*2 + s)]
//   tile nt = np*2 + t, n = nt*8 + lane/4, k = kt*16 + s*8 + 2*(lane%4) (+1)
__device__ uint32_t g_Kp [ 8 *  8 * 128];   // cross_k    K=128 N=128
__device__ uint32_t g_K2p[ 8 *  8 * 128];   // cross_k^2
__device__ uint32_t g_W1p[ 8 * 13 * 128];   // W1 128->208
__device__ uint32_t g_W2p[13 * 16 * 128];   // W2 208->256
__device__ uint32_t g_W3p[16 * 13 * 128];   // W3 256->208
__device__ uint32_t g_W4p[13 *  8 * 128];   // W4 208->128
__device__ float    g_b1p[208];
__device__ float    g_b2p[256];
__device__ float    g_b3p[208];
__device__ float    g_b4p[128];

__device__ __forceinline__ uint32_t pack_bf2(float lo, float hi) {
    __nv_bfloat162 h = __floats2bfloat162_rn(lo, hi);
    return *reinterpret_cast<uint32_t*>(&h);
}

__device__ __forceinline__ void mma_bf16(float d[4],
                                         uint32_t a0, uint32_t a1, uint32_t a2, uint32_t a3,
                                         uint32_t b0, uint32_t b1) {
    asm volatile(
        "mma.sync.aligned.m16n8k16.row.col.f32.bf16.bf16.f32 "
        "{%0,%1,%2,%3}, {%4,%5,%6,%7}, {%8,%9}, {%0,%1,%2,%3};\n"
        : "+f"(d[0]), "+f"(d[1]), "+f"(d[2]), "+f"(d[3])
        : "r"(a0), "r"(a1), "r"(a2), "r"(a3), "r"(b0), "r"(b1));
}

// ---------------- prep kernel ---------------------------------------------
__device__ __forceinline__ void pack_w(uint32_t* dst, const float* __restrict__ src,
                                       int K_real, int N_real, int NP, int idx, bool square) {
    const int j    = idx & 3;
    const int lane = (idx >> 2) & 31;
    const int tp   = idx >> 7;
    const int np   = tp % NP;
    const int kt   = tp / NP;
    const int t = j >> 1, s = j & 1;
    const int n  = (np * 2 + t) * 8 + (lane >> 2);
    const int k0 = kt * 16 + s * 8 + 2 * (lane & 3);
    float v0 = (k0     < K_real && n < N_real) ? src[(size_t)k0 * N_real + n]       : 0.0f;
    float v1 = (k0 + 1 < K_real && n < N_real) ? src[(size_t)(k0 + 1) * N_real + n] : 0.0f;
    if (square) { v0 *= v0; v1 *= v1; }
    dst[idx] = pack_bf2(v0, v1);
}

#define SZ_KP  (8 * 8 * 128)
#define SZ_W1  (8 * 13 * 128)
#define SZ_W2  (13 * 16 * 128)
#define SZ_W3  (16 * 13 * 128)
#define SZ_W4  (13 * 8 * 128)

__global__ void pack_kernel(const float* __restrict__ cross_k,
                            const float* __restrict__ W1, const float* __restrict__ W2,
                            const float* __restrict__ W3, const float* __restrict__ W4,
                            const float* __restrict__ b1, const float* __restrict__ b2,
                            const float* __restrict__ b3, const float* __restrict__ b4) {
    const int i = blockIdx.x * blockDim.x + threadIdx.x;
    const int E0 = SZ_KP, E1 = E0 + SZ_KP, E2 = E1 + SZ_W1, E3 = E2 + SZ_W2;
    const int E4 = E3 + SZ_W3, E5 = E4 + SZ_W4;
    if      (i < E0) pack_w(g_Kp,  cross_k, 128, 128,  8, i,      false);
    else if (i < E1) pack_w(g_K2p, cross_k, 128, 128,  8, i - E0, true);
    else if (i < E2) pack_w(g_W1p, W1,      128, 200, 13, i - E1, false);
    else if (i < E3) pack_w(g_W2p, W2,      200, 256, 16, i - E2, false);
    else if (i < E4) pack_w(g_W3p, W3,      256, 200, 13, i - E3, false);
    else if (i < E5) pack_w(g_W4p, W4,      200, 128,  8, i - E4, false);
    else {
        int j = i - E5;
        if      (j < 208) g_b1p[j]       = (j < 200) ? b1[j] : 0.0f;
        else if (j < 464) g_b2p[j - 208] = b2[j - 208];
        else if (j < 672) g_b3p[j - 464] = (j - 464 < 200) ? b3[j - 464] : 0.0f;
        else if (j < 800) g_b4p[j - 672] = b4[j - 672];
    }
}
#define PACK_TOTAL (SZ_KP + SZ_KP + SZ_W1 + SZ_W2 + SZ_W3 + SZ_W4 + 800)

// ---------------- GEMM chunk: 32 rows (2 m-groups) x NPAIR pairs ----------
template<int NPAIR, bool F32OUT>
__device__ __forceinline__ void gemm_chunk(
    const uint32_t* __restrict__ Xw, int xs,
    void* __restrict__ Yout, int ys,
    const uint32_t* __restrict__ Wp, const float* __restrict__ biasp,
    int KT, int NP, int row0, int np0, int lane)
{
    const int NT = NPAIR * 2;
    float acc[NT][2][4];
#pragma unroll
    for (int t = 0; t < NT; t++)
#pragma unroll
        for (int mg = 0; mg < 2; mg++)
            acc[t][mg][0] = acc[t][mg][1] = acc[t][mg][2] = acc[t][mg][3] = 0.0f;

    const int gid = lane >> 2, tig = lane & 3;
    const uint32_t* xr[2][2];
#pragma unroll
    for (int mg = 0; mg < 2; mg++) {
        xr[mg][0] = Xw + (row0 + mg * 16 + gid)     * xs;
        xr[mg][1] = Xw + (row0 + mg * 16 + gid + 8) * xs;
    }

    for (int kt = 0; kt < KT; kt++) {
        const int wd = kt * 8 + tig;
        uint32_t a[2][4];
#pragma unroll
        for (int mg = 0; mg < 2; mg++) {
            a[mg][0] = xr[mg][0][wd];
            a[mg][1] = xr[mg][1][wd];
            a[mg][2] = xr[mg][0][wd + 4];
            a[mg][3] = xr[mg][1][wd + 4];
        }
        const uint4* bp = reinterpret_cast<const uint4*>(Wp + (((size_t)kt * NP + np0) * 32 + lane) * 4);
#pragma unroll
        for (int p = 0; p < NPAIR; p++) {
            const uint4 B = bp[p * 32];
#pragma unroll
            for (int mg = 0; mg < 2; mg++) {
                mma_bf16(acc[p * 2][mg],     a[mg][0], a[mg][1], a[mg][2], a[mg][3], B.x, B.y);
                mma_bf16(acc[p * 2 + 1][mg], a[mg][0], a[mg][1], a[mg][2], a[mg][3], B.z, B.w);
            }
        }
    }
#pragma unroll
    for (int t = 0; t < NT; t++) {
        const int nt  = np0 * 2 + t;
        const int col = nt * 8 + 2 * tig;
        const float bc0 = biasp[col], bc1 = biasp[col + 1];
#pragma unroll
        for (int mg = 0; mg < 2; mg++) {
            const int rbase = row0 + mg * 16;
            float v0 = fmaxf(acc[t][mg][0] + bc0, 0.0f);
            float v1 = fmaxf(acc[t][mg][1] + bc1, 0.0f);
            float v2 = fmaxf(acc[t][mg][2] + bc0, 0.0f);
            float v3 = fmaxf(acc[t][mg][3] + bc1, 0.0f);
            if (F32OUT) {
                float* Y = reinterpret_cast<float*>(Yout);
                Y[(rbase + gid)     * ys + col]     = v0;
                Y[(rbase + gid)     * ys + col + 1] = v1;
                Y[(rbase + gid + 8) * ys + col]     = v2;
                Y[(rbase + gid + 8) * ys + col + 1] = v3;
            } else {
                uint32_t* Y = reinterpret_cast<uint32_t*>(Yout);
                Y[(rbase + gid)     * ys + nt * 4 + tig] = pack_bf2(v0, v1);
                Y[(rbase + gid + 8) * ys + nt * 4 + tig] = pack_bf2(v2, v3);
            }
        }
    }
}

template<bool F32OUT>
__device__ __forceinline__ void gemm_range(
    const uint32_t* __restrict__ Xw, int xs, void* __restrict__ Yout, int ys,
    const uint32_t* __restrict__ Wp, const float* __restrict__ biasp,
    int KT, int NP, int row0, int np_begin, int np_end, int lane)
{
    int np = np_begin;
    int rem = np_end - np;
    while (rem >= 4) {
        gemm_chunk<4, F32OUT>(Xw, xs, Yout, ys, Wp, biasp, KT, NP, row0, np, lane);
        np += 4; rem -= 4;
    }
    if (rem == 3)      gemm_chunk<3, F32OUT>(Xw, xs, Yout, ys, Wp, biasp, KT, NP, row0, np, lane);
    else if (rem == 2) gemm_chunk<2, F32OUT>(Xw, xs, Yout, ys, Wp, biasp, KT, NP, row0, np, lane);
    else if (rem == 1) gemm_chunk<1, F32OUT>(Xw, xs, Yout, ys, Wp, biasp, KT, NP, row0, np, lane);
}

// ---------------- FM cross: one pair (2 tiles) x 32 rows, P & Q -----------
__device__ __forceinline__ void cross_pair(
    const uint32_t* __restrict__ X0, const uint32_t* __restrict__ X0sq,
    int row0, int np0, int lane, float s[4])
{
    float p[2][2][4], q[2][2][4];
#pragma unroll
    for (int t = 0; t < 2; t++)
#pragma unroll
        for (int mg = 0; mg < 2; mg++) {
            p[t][mg][0] = p[t][mg][1] = p[t][mg][2] = p[t][mg][3] = 0.0f;
            q[t][mg][0] = q[t][mg][1] = q[t][mg][2] = q[t][mg][3] = 0.0f;
        }
    const int gid = lane >> 2, tig = lane & 3;
    const uint32_t *xr[2][2], *ur[2][2];
#pragma unroll
    for (int mg = 0; mg < 2; mg++) {
        xr[mg][0] = X0   + (row0 + mg * 16 + gid)     * W128;
        xr[mg][1] = X0   + (row0 + mg * 16 + gid + 8) * W128;
        ur[mg][0] = X0sq + (row0 + mg * 16 + gid)     * W128;
        ur[mg][1] = X0sq + (row0 + mg * 16 + gid + 8) * W128;
    }
    for (int kt = 0; kt < 8; kt++) {
        const int wd = kt * 8 + tig;
        const size_t off = (((size_t)kt * 8 + np0) * 32 + lane) * 4;
        const uint4 B1 = *reinterpret_cast<const uint4*>(g_Kp  + off);
        const uint4 B2 = *reinterpret_cast<const uint4*>(g_K2p + off);
#pragma unroll
        for (int mg = 0; mg < 2; mg++) {
            const uint32_t a0 = xr[mg][0][wd], a1 = xr[mg][1][wd];
            const uint32_t a2 = xr[mg][0][wd + 4], a3 = xr[mg][1][wd + 4];
            const uint32_t u0 = ur[mg][0][wd], u1 = ur[mg][1][wd];
            const uint32_t u2 = ur[mg][0][wd + 4], u3 = ur[mg][1][wd + 4];
            mma_bf16(p[0][mg], a0, a1, a2, a3, B1.x, B1.y);
            mma_bf16(p[1][mg], a0, a1, a2, a3, B1.z, B1.w);
            mma_bf16(q[0][mg], u0, u1, u2, u3, B2.x, B2.y);
            mma_bf16(q[1][mg], u0, u1, u2, u3, B2.z, B2.w);
        }
    }
#pragma unroll
    for (int t = 0; t < 2; t++)
#pragma unroll
        for (int mg = 0; mg < 2; mg++) {
            s[mg * 2]     += p[t][mg][0] * p[t][mg][0] - q[t][mg][0]
                           + p[t][mg][1] * p[t][mg][1] - q[t][mg][1];
            s[mg * 2 + 1] += p[t][mg][2] * p[t][mg][2] - q[t][mg][2]
                           + p[t][mg][3] * p[t][mg][3] - q[t][mg][3];
        }
}

// ---------------- main kernel ---------------------------------------------
__global__ __launch_bounds__(NTHREADS, 2)
void dfm_bf16_kernel(
    const int* __restrict__ user_idx, const int* __restrict__ item_idx,
    const float* __restrict__ user_emb, const float* __restrict__ item_emb,
    const float* __restrict__ lin_w, const float* __restrict__ lin_b,
    const float* __restrict__ W5, const float* __restrict__ b5,
    float* __restrict__ out)
{
    extern __shared__ uint32_t smem[];
    uint32_t* arenaA = smem;
    uint32_t* arenaB = arenaA + 2 * M_TILE * W128;
    uint32_t* arenaC = arenaB + M_TILE * W208;
    float*    rowacc = reinterpret_cast<float*>(arenaC + M_TILE * W256);

    uint32_t* X0    = arenaA;
    uint32_t* X0sq  = arenaA + M_TILE * W128;
    uint32_t* ping  = arenaB;
    uint32_t* pong  = arenaC;
    uint32_t* ping2 = arenaA;                           // L3 out, stride W208
    float*    X4    = reinterpret_cast<float*>(arenaC); // L4 out fp32, stride F128

    const int tid   = threadIdx.x;
    const int lane  = tid & 31;
    const int w     = tid >> 5;
    const int row0  = (w & 1) * 32;     // m-group of 32 rows
    const int nq    = w >> 1;           // n-quarter 0..3
    const int grow0 = blockIdx.x * M_TILE;

    // ---- gather embeddings -> bf16 words + squares; FM linear ----
    for (int i = tid; i < M_TILE * 64; i += NTHREADS) {
        const int r = i >> 6;
        const int wd = i & 63;
        const int g = grow0 + r;
        float2 v;
        if (wd < 32) v = *reinterpret_cast<const float2*>(&user_emb[(size_t)user_idx[g] * 64 + 2 * wd]);
        else         v = *reinterpret_cast<const float2*>(&item_emb[(size_t)item_idx[g] * 64 + 2 * (wd - 32)]);
        const float x0 = __bfloat162float(__float2bfloat16_rn(v.x));
        const float x1 = __bfloat162float(__float2bfloat16_rn(v.y));
        X0  [r * W128 + wd] = pack_bf2(x0, x1);
        X0sq[r * W128 + wd] = pack_bf2(x0 * x0, x1 * x1);
    }
    for (int r = tid; r < M_TILE; r += NTHREADS) {
        const int g = grow0 + r;
        rowacc[r] = __ldg(&lin_w[user_idx[g]]) + __ldg(&lin_w[HASH_BINS + item_idx[g]])
                  + __ldg(&lin_b[0]);
    }
    __syncthreads();

    // ---- FM cross: N=128 -> 8 pairs, 2 per n-quarter ----
    {
        float s[4] = {0.0f, 0.0f, 0.0f, 0.0f};
        cross_pair(X0, X0sq, row0, 2 * nq,     lane, s);
        cross_pair(X0, X0sq, row0, 2 * nq + 1, lane, s);
#pragma unroll
        for (int i = 0; i < 4; i++) {
            s[i] += __shfl_xor_sync(0xffffffffu, s[i], 1);
            s[i] += __shfl_xor_sync(0xffffffffu, s[i], 2);
        }
        if ((lane & 3) == 0) {
            const int gid = lane >> 2;
            const float sc = 0.5f / 128.0f;
            atomicAdd(&rowacc[row0 + gid],          sc * s[0]);
            atomicAdd(&rowacc[row0 + gid + 8],      sc * s[1]);
            atomicAdd(&rowacc[row0 + 16 + gid],     sc * s[2]);
            atomicAdd(&rowacc[row0 + 16 + gid + 8], sc * s[3]);
        }
    }

    // ---- L1: 128 -> 208, X0 -> ping.  Pairs: 4/3/3/3 per quarter ----
    {
        const int begin = (nq == 0) ? 0 : (4 + 3 * (nq - 1));
        const int end   = begin + ((nq == 0) ? 4 : 3);
        gemm_range<false>(X0, W128, ping, W208, g_W1p, g_b1p, 8, 13, row0, begin, end, lane);
    }
    __syncthreads();

    // ---- L2: 208 -> 256, ping -> pong.  4 pairs per quarter ----
    gemm_range<false>(ping, W208, pong, W256, g_W2p, g_b2p, 13, 16, row0, 4 * nq, 4 * nq + 4, lane);
    __syncthreads();

    // ---- L3: 256 -> 208, pong -> ping2 (arenaA reused) ----
    {
        const int begin = (nq == 0) ? 0 : (4 + 3 * (nq - 1));
        const int end   = begin + ((nq == 0) ? 4 : 3);
        gemm_range<false>(pong, W256, ping2, W208, g_W3p, g_b3p, 16, 13, row0, begin, end, lane);
    }
    __syncthreads();

    // ---- L4: 208 -> 128, ping2 -> X4 (fp32, arenaC reused).  2 pairs ----
    gemm_range<true>(ping2, W208, X4, F128, g_W4p, g_b4p, 13, 8, row0, 2 * nq, 2 * nq + 2, lane);
    __syncthreads();

    // ---- L5: Dense(1) + linear + cross + sigmoid ----
    if (tid < M_TILE) {
        const int r = tid;
        float acc = __ldg(&b5[0]);
#pragma unroll 8
        for (int k = 0; k < 128; k++)
            acc = fmaf(X4[r * F128 + k], __ldg(&W5[k]), acc);
        const float logit = acc + rowacc[r];
        out[grow0 + r] = 1.0f / (1.0f + expf(-logit));
    }
}

extern "C" void kernel_launch(void* const* d_in, const int* in_sizes, int n_in,
                              void* d_out, int out_size)
{
    const int*   user_idx = (const int*)d_in[0];
    const int*   item_idx = (const int*)d_in[1];
    const float* user_emb = (const float*)d_in[2];
    const float* item_emb = (const float*)d_in[3];
    const float* lin_w    = (const float*)d_in[4];
    const float* lin_b    = (const float*)d_in[5];
    const float* cross_k  = (const float*)d_in[6];
    const float* W1 = (const float*)d_in[7];  const float* b1 = (const float*)d_in[8];
    const float* W2 = (const float*)d_in[9];  const float* b2 = (const float*)d_in[10];
    const float* W3 = (const float*)d_in[11]; const float* b3 = (const float*)d_in[12];
    const float* W4 = (const float*)d_in[13]; const float* b4 = (const float*)d_in[14];
    const float* W5 = (const float*)d_in[15]; const float* b5 = (const float*)d_in[16];
    float* out = (float*)d_out;

    const int B = in_sizes[0];

    pack_kernel<<<(PACK_TOTAL + 255) / 256, 256>>>(cross_k, W1, W2, W3, W4, b1, b2, b3, b4);

    const int smem_words = 2 * M_TILE * W128 + M_TILE * W208 + M_TILE * W256 + M_TILE;
    const int smem_bytes = smem_words * 4;   // ~94.5 KB

    cudaFuncSetAttribute(dfm_bf16_kernel, cudaFuncAttributeMaxDynamicSharedMemorySize, smem_bytes);

    dfm_bf16_kernel<<<B / M_TILE, NTHREADS, smem_bytes>>>(
        user_idx, item_idx, user_emb, item_emb, lin_w, lin_b, W5, b5, out);
}

// round 8
// speedup vs baseline: 31.7719x; 1.0001x over previous
#include <cuda_runtime.h>
#include <cuda_bf16.h>
#include <math.h>
#include <stdint.h>

// DeepFM fused inference — bf16 m16n8k16, M=32 per warp (B-reuse doubled).
// Per CTA: 64 rows, 8 warps = 2 row-groups(32) x 4 n-quarters.
// Weights pre-packed (pair-of-tiles -> one LDG.128) by a prep kernel.

#define HASH_BINS 100000
#define M_TILE 64
#define NTHREADS 256

// Activation smem strides in 32-bit WORDS (2 bf16 per word).
// stride % 8 == 4 -> conflict-free A-fragment LDS and epilogue STS.
#define W128 68
#define W208 108
#define W256 132
#define F128 132   // fp32 stride for final activation buffer

// ---------------- packed weight scratch (device globals) -------------------
// word[(((kt*NP + np)*32 + lane)*4 + t*2 + s)]
//   tile nt = np*2 + t, n = nt*8 + lane/4, k = kt*16 + s*8 + 2*(lane%4) (+1)
__device__ uint32_t g_Kp [ 8 *  8 * 128];   // cross_k    K=128 N=128
__device__ uint32_t g_K2p[ 8 *  8 * 128];   // cross_k^2
__device__ uint32_t g_W1p[ 8 * 13 * 128];   // W1 128->208
__device__ uint32_t g_W2p[13 * 16 * 128];   // W2 208->256
__device__ uint32_t g_W3p[16 * 13 * 128];   // W3 256->208
__device__ uint32_t g_W4p[13 *  8 * 128];   // W4 208->128
__device__ float    g_b1p[208];
__device__ float    g_b2p[256];
__device__ float    g_b3p[208];
__device__ float    g_b4p[128];

__device__ __forceinline__ uint32_t pack_bf2(float lo, float hi) {
    __nv_bfloat162 h = __floats2bfloat162_rn(lo, hi);
    return *reinterpret_cast<uint32_t*>(&h);
}

__device__ __forceinline__ void mma_bf16(float d[4],
                                         uint32_t a0, uint32_t a1, uint32_t a2, uint32_t a3,
                                         uint32_t b0, uint32_t b1) {
    asm volatile(
        "mma.sync.aligned.m16n8k16.row.col.f32.bf16.bf16.f32 "
        "{%0,%1,%2,%3}, {%4,%5,%6,%7}, {%8,%9}, {%0,%1,%2,%3};\n"
        : "+f"(d[0]), "+f"(d[1]), "+f"(d[2]), "+f"(d[3])
        : "r"(a0), "r"(a1), "r"(a2), "r"(a3), "r"(b0), "r"(b1));
}

// ---------------- prep kernel ---------------------------------------------
__device__ __forceinline__ void pack_w(uint32_t* dst, const float* __restrict__ src,
                                       int K_real, int N_real, int NP, int idx, bool square) {
    const int j    = idx & 3;
    const int lane = (idx >> 2) & 31;
    const int tp   = idx >> 7;
    const int np   = tp % NP;
    const int kt   = tp / NP;
    const int t = j >> 1, s = j & 1;
    const int n  = (np * 2 + t) * 8 + (lane >> 2);
    const int k0 = kt * 16 + s * 8 + 2 * (lane & 3);
    float v0 = (k0     < K_real && n < N_real) ? src[(size_t)k0 * N_real + n]       : 0.0f;
    float v1 = (k0 + 1 < K_real && n < N_real) ? src[(size_t)(k0 + 1) * N_real + n] : 0.0f;
    if (square) { v0 *= v0; v1 *= v1; }
    dst[idx] = pack_bf2(v0, v1);
}

#define SZ_KP  (8 * 8 * 128)
#define SZ_W1  (8 * 13 * 128)
#define SZ_W2  (13 * 16 * 128)
#define SZ_W3  (16 * 13 * 128)
#define SZ_W4  (13 * 8 * 128)

__global__ void pack_kernel(const float* __restrict__ cross_k,
                            const float* __restrict__ W1, const float* __restrict__ W2,
                            const float* __restrict__ W3, const float* __restrict__ W4,
                            const float* __restrict__ b1, const float* __restrict__ b2,
                            const float* __restrict__ b3, const float* __restrict__ b4) {
    const int i = blockIdx.x * blockDim.x + threadIdx.x;
    const int E0 = SZ_KP, E1 = E0 + SZ_KP, E2 = E1 + SZ_W1, E3 = E2 + SZ_W2;
    const int E4 = E3 + SZ_W3, E5 = E4 + SZ_W4;
    if      (i < E0) pack_w(g_Kp,  cross_k, 128, 128,  8, i,      false);
    else if (i < E1) pack_w(g_K2p, cross_k, 128, 128,  8, i - E0, true);
    else if (i < E2) pack_w(g_W1p, W1,      128, 200, 13, i - E1, false);
    else if (i < E3) pack_w(g_W2p, W2,      200, 256, 16, i - E2, false);
    else if (i < E4) pack_w(g_W3p, W3,      256, 200, 13, i - E3, false);
    else if (i < E5) pack_w(g_W4p, W4,      200, 128,  8, i - E4, false);
    else {
        int j = i - E5;
        if      (j < 208) g_b1p[j]       = (j < 200) ? b1[j] : 0.0f;
        else if (j < 464) g_b2p[j - 208] = b2[j - 208];
        else if (j < 672) g_b3p[j - 464] = (j - 464 < 200) ? b3[j - 464] : 0.0f;
        else if (j < 800) g_b4p[j - 672] = b4[j - 672];
    }
}
#define PACK_TOTAL (SZ_KP + SZ_KP + SZ_W1 + SZ_W2 + SZ_W3 + SZ_W4 + 800)

// ---------------- GEMM chunk: 32 rows (2 m-groups) x NPAIR pairs ----------
template<int NPAIR, bool F32OUT>
__device__ __forceinline__ void gemm_chunk(
    const uint32_t* __restrict__ Xw, int xs,
    void* __restrict__ Yout, int ys,
    const uint32_t* __restrict__ Wp, const float* __restrict__ biasp,
    int KT, int NP, int row0, int np0, int lane)
{
    const int NT = NPAIR * 2;
    float acc[NT][2][4];
#pragma unroll
    for (int t = 0; t < NT; t++)
#pragma unroll
        for (int mg = 0; mg < 2; mg++)
            acc[t][mg][0] = acc[t][mg][1] = acc[t][mg][2] = acc[t][mg][3] = 0.0f;

    const int gid = lane >> 2, tig = lane & 3;
    const uint32_t* xr[2][2];
#pragma unroll
    for (int mg = 0; mg < 2; mg++) {
        xr[mg][0] = Xw + (row0 + mg * 16 + gid)     * xs;
        xr[mg][1] = Xw + (row0 + mg * 16 + gid + 8) * xs;
    }

    for (int kt = 0; kt < KT; kt++) {
        const int wd = kt * 8 + tig;
        uint32_t a[2][4];
#pragma unroll
        for (int mg = 0; mg < 2; mg++) {
            a[mg][0] = xr[mg][0][wd];
            a[mg][1] = xr[mg][1][wd];
            a[mg][2] = xr[mg][0][wd + 4];
            a[mg][3] = xr[mg][1][wd + 4];
        }
        const uint4* bp = reinterpret_cast<const uint4*>(Wp + (((size_t)kt * NP + np0) * 32 + lane) * 4);
#pragma unroll
        for (int p = 0; p < NPAIR; p++) {
            const uint4 B = bp[p * 32];
#pragma unroll
            for (int mg = 0; mg < 2; mg++) {
                mma_bf16(acc[p * 2][mg],     a[mg][0], a[mg][1], a[mg][2], a[mg][3], B.x, B.y);
                mma_bf16(acc[p * 2 + 1][mg], a[mg][0], a[mg][1], a[mg][2], a[mg][3], B.z, B.w);
            }
        }
    }
#pragma unroll
    for (int t = 0; t < NT; t++) {
        const int nt  = np0 * 2 + t;
        const int col = nt * 8 + 2 * tig;
        const float bc0 = biasp[col], bc1 = biasp[col + 1];
#pragma unroll
        for (int mg = 0; mg < 2; mg++) {
            const int rbase = row0 + mg * 16;
            float v0 = fmaxf(acc[t][mg][0] + bc0, 0.0f);
            float v1 = fmaxf(acc[t][mg][1] + bc1, 0.0f);
            float v2 = fmaxf(acc[t][mg][2] + bc0, 0.0f);
            float v3 = fmaxf(acc[t][mg][3] + bc1, 0.0f);
            if (F32OUT) {
                float* Y = reinterpret_cast<float*>(Yout);
                Y[(rbase + gid)     * ys + col]     = v0;
                Y[(rbase + gid)     * ys + col + 1] = v1;
                Y[(rbase + gid + 8) * ys + col]     = v2;
                Y[(rbase + gid + 8) * ys + col + 1] = v3;
            } else {
                uint32_t* Y = reinterpret_cast<uint32_t*>(Yout);
                Y[(rbase + gid)     * ys + nt * 4 + tig] = pack_bf2(v0, v1);
                Y[(rbase + gid + 8) * ys + nt * 4 + tig] = pack_bf2(v2, v3);
            }
        }
    }
}

template<bool F32OUT>
__device__ __forceinline__ void gemm_range(
    const uint32_t* __restrict__ Xw, int xs, void* __restrict__ Yout, int ys,
    const uint32_t* __restrict__ Wp, const float* __restrict__ biasp,
    int KT, int NP, int row0, int np_begin, int np_end, int lane)
{
    int np = np_begin;
    int rem = np_end - np;
    while (rem >= 4) {
        gemm_chunk<4, F32OUT>(Xw, xs, Yout, ys, Wp, biasp, KT, NP, row0, np, lane);
        np += 4; rem -= 4;
    }
    if (rem == 3)      gemm_chunk<3, F32OUT>(Xw, xs, Yout, ys, Wp, biasp, KT, NP, row0, np, lane);
    else if (rem == 2) gemm_chunk<2, F32OUT>(Xw, xs, Yout, ys, Wp, biasp, KT, NP, row0, np, lane);
    else if (rem == 1) gemm_chunk<1, F32OUT>(Xw, xs, Yout, ys, Wp, biasp, KT, NP, row0, np, lane);
}

// ---------------- FM cross: one pair (2 tiles) x 32 rows, P & Q -----------
__device__ __forceinline__ void cross_pair(
    const uint32_t* __restrict__ X0, const uint32_t* __restrict__ X0sq,
    int row0, int np0, int lane, float s[4])
{
    float p[2][2][4], q[2][2][4];
#pragma unroll
    for (int t = 0; t < 2; t++)
#pragma unroll
        for (int mg = 0; mg < 2; mg++) {
            p[t][mg][0] = p[t][mg][1] = p[t][mg][2] = p[t][mg][3] = 0.0f;
            q[t][mg][0] = q[t][mg][1] = q[t][mg][2] = q[t][mg][3] = 0.0f;
        }
    const int gid = lane >> 2, tig = lane & 3;
    const uint32_t *xr[2][2], *ur[2][2];
#pragma unroll
    for (int mg = 0; mg < 2; mg++) {
        xr[mg][0] = X0   + (row0 + mg * 16 + gid)     * W128;
        xr[mg][1] = X0   + (row0 + mg * 16 + gid + 8) * W128;
        ur[mg][0] = X0sq + (row0 + mg * 16 + gid)     * W128;
        ur[mg][1] = X0sq + (row0 + mg * 16 + gid + 8) * W128;
    }
    for (int kt = 0; kt < 8; kt++) {
        const int wd = kt * 8 + tig;
        const size_t off = (((size_t)kt * 8 + np0) * 32 + lane) * 4;
        const uint4 B1 = *reinterpret_cast<const uint4*>(g_Kp  + off);
        const uint4 B2 = *reinterpret_cast<const uint4*>(g_K2p + off);
#pragma unroll
        for (int mg = 0; mg < 2; mg++) {
            const uint32_t a0 = xr[mg][0][wd], a1 = xr[mg][1][wd];
            const uint32_t a2 = xr[mg][0][wd + 4], a3 = xr[mg][1][wd + 4];
            const uint32_t u0 = ur[mg][0][wd], u1 = ur[mg][1][wd];
            const uint32_t u2 = ur[mg][0][wd + 4], u3 = ur[mg][1][wd + 4];
            mma_bf16(p[0][mg], a0, a1, a2, a3, B1.x, B1.y);
            mma_bf16(p[1][mg], a0, a1, a2, a3, B1.z, B1.w);
            mma_bf16(q[0][mg], u0, u1, u2, u3, B2.x, B2.y);
            mma_bf16(q[1][mg], u0, u1, u2, u3, B2.z, B2.w);
        }
    }
#pragma unroll
    for (int t = 0; t < 2; t++)
#pragma unroll
        for (int mg = 0; mg < 2; mg++) {
            s[mg * 2]     += p[t][mg][0] * p[t][mg][0] - q[t][mg][0]
                           + p[t][mg][1] * p[t][mg][1] - q[t][mg][1];
            s[mg * 2 + 1] += p[t][mg][2] * p[t][mg][2] - q[t][mg][2]
                           + p[t][mg][3] * p[t][mg][3] - q[t][mg][3];
        }
}

// ---------------- main kernel ---------------------------------------------
__global__ __launch_bounds__(NTHREADS, 2)
void dfm_bf16_kernel(
    const int* __restrict__ user_idx, const int* __restrict__ item_idx,
    const float* __restrict__ user_emb, const float* __restrict__ item_emb,
    const float* __restrict__ lin_w, const float* __restrict__ lin_b,
    const float* __restrict__ W5, const float* __restrict__ b5,
    float* __restrict__ out)
{
    extern __shared__ uint32_t smem[];
    uint32_t* arenaA = smem;
    uint32_t* arenaB = arenaA + 2 * M_TILE * W128;
    uint32_t* arenaC = arenaB + M_TILE * W208;
    float*    rowacc = reinterpret_cast<float*>(arenaC + M_TILE * W256);

    uint32_t* X0    = arenaA;
    uint32_t* X0sq  = arenaA + M_TILE * W128;
    uint32_t* ping  = arenaB;
    uint32_t* pong  = arenaC;
    uint32_t* ping2 = arenaA;                           // L3 out, stride W208
    float*    X4    = reinterpret_cast<float*>(arenaC); // L4 out fp32, stride F128

    const int tid   = threadIdx.x;
    const int lane  = tid & 31;
    const int w     = tid >> 5;
    const int row0  = (w & 1) * 32;     // m-group of 32 rows
    const int nq    = w >> 1;           // n-quarter 0..3
    const int grow0 = blockIdx.x * M_TILE;

    // ---- gather embeddings -> bf16 words + squares; FM linear ----
    for (int i = tid; i < M_TILE * 64; i += NTHREADS) {
        const int r = i >> 6;
        const int wd = i & 63;
        const int g = grow0 + r;
        float2 v;
        if (wd < 32) v = *reinterpret_cast<const float2*>(&user_emb[(size_t)user_idx[g] * 64 + 2 * wd]);
        else         v = *reinterpret_cast<const float2*>(&item_emb[(size_t)item_idx[g] * 64 + 2 * (wd - 32)]);
        const float x0 = __bfloat162float(__float2bfloat16_rn(v.x));
        const float x1 = __bfloat162float(__float2bfloat16_rn(v.y));
        X0  [r * W128 + wd] = pack_bf2(x0, x1);
        X0sq[r * W128 + wd] = pack_bf2(x0 * x0, x1 * x1);
    }
    for (int r = tid; r < M_TILE; r += NTHREADS) {
        const int g = grow0 + r;
        rowacc[r] = __ldg(&lin_w[user_idx[g]]) + __ldg(&lin_w[HASH_BINS + item_idx[g]])
                  + __ldg(&lin_b[0]);
    }
    __syncthreads();

    // ---- FM cross: N=128 -> 8 pairs, 2 per n-quarter ----
    {
        float s[4] = {0.0f, 0.0f, 0.0f, 0.0f};
        cross_pair(X0, X0sq, row0, 2 * nq,     lane, s);
        cross_pair(X0, X0sq, row0, 2 * nq + 1, lane, s);
#pragma unroll
        for (int i = 0; i < 4; i++) {
            s[i] += __shfl_xor_sync(0xffffffffu, s[i], 1);
            s[i] += __shfl_xor_sync(0xffffffffu, s[i], 2);
        }
        if ((lane & 3) == 0) {
            const int gid = lane >> 2;
            const float sc = 0.5f / 128.0f;
            atomicAdd(&rowacc[row0 + gid],          sc * s[0]);
            atomicAdd(&rowacc[row0 + gid + 8],      sc * s[1]);
            atomicAdd(&rowacc[row0 + 16 + gid],     sc * s[2]);
            atomicAdd(&rowacc[row0 + 16 + gid + 8], sc * s[3]);
        }
    }

    // ---- L1: 128 -> 208, X0 -> ping.  Pairs: 4/3/3/3 per quarter ----
    {
        const int begin = (nq == 0) ? 0 : (4 + 3 * (nq - 1));
        const int end   = begin + ((nq == 0) ? 4 : 3);
        gemm_range<false>(X0, W128, ping, W208, g_W1p, g_b1p, 8, 13, row0, begin, end, lane);
    }
    __syncthreads();

    // ---- L2: 208 -> 256, ping -> pong.  4 pairs per quarter ----
    gemm_range<false>(ping, W208, pong, W256, g_W2p, g_b2p, 13, 16, row0, 4 * nq, 4 * nq + 4, lane);
    __syncthreads();

    // ---- L3: 256 -> 208, pong -> ping2 (arenaA reused) ----
    {
        const int begin = (nq == 0) ? 0 : (4 + 3 * (nq - 1));
        const int end   = begin + ((nq == 0) ? 4 : 3);
        gemm_range<false>(pong, W256, ping2, W208, g_W3p, g_b3p, 16, 13, row0, begin, end, lane);
    }
    __syncthreads();

    // ---- L4: 208 -> 128, ping2 -> X4 (fp32, arenaC reused).  2 pairs ----
    gemm_range<true>(ping2, W208, X4, F128, g_W4p, g_b4p, 13, 8, row0, 2 * nq, 2 * nq + 2, lane);
    __syncthreads();

    // ---- L5: Dense(1) + linear + cross + sigmoid ----
    if (tid < M_TILE) {
        const int r = tid;
        float acc = __ldg(&b5[0]);
#pragma unroll 8
        for (int k = 0; k < 128; k++)
            acc = fmaf(X4[r * F128 + k], __ldg(&W5[k]), acc);
        const float logit = acc + rowacc[r];
        out[grow0 + r] = 1.0f / (1.0f + expf(-logit));
    }
}

extern "C" void kernel_launch(void* const* d_in, const int* in_sizes, int n_in,
                              void* d_out, int out_size)
{
    const int*   user_idx = (const int*)d_in[0];
    const int*   item_idx = (const int*)d_in[1];
    const float* user_emb = (const float*)d_in[2];
    const float* item_emb = (const float*)d_in[3];
    const float* lin_w    = (const float*)d_in[4];
    const float* lin_b    = (const float*)d_in[5];
    const float* cross_k  = (const float*)d_in[6];
    const float* W1 = (const float*)d_in[7];  const float* b1 = (const float*)d_in[8];
    const float* W2 = (const float*)d_in[9];  const float* b2 = (const float*)d_in[10];
    const float* W3 = (const float*)d_in[11]; const float* b3 = (const float*)d_in[12];
    const float* W4 = (const float*)d_in[13]; const float* b4 = (const float*)d_in[14];
    const float* W5 = (const float*)d_in[15]; const float* b5 = (const float*)d_in[16];
    float* out = (float*)d_out;

    const int B = in_sizes[0];

    pack_kernel<<<(PACK_TOTAL + 255) / 256, 256>>>(cross_k, W1, W2, W3, W4, b1, b2, b3, b4);

    const int smem_words = 2 * M_TILE * W128 + M_TILE * W208 + M_TILE * W256 + M_TILE;
    const int smem_bytes = smem_words * 4;   // ~94.5 KB

    cudaFuncSetAttribute(dfm_bf16_kernel, cudaFuncAttributeMaxDynamicSharedMemorySize, smem_bytes);

    dfm_bf16_kernel<<<B / M_TILE, NTHREADS, smem_bytes>>>(
        user_idx, item_idx, user_emb, item_emb, lin_w, lin_b, W5, b5, out);
}